// round 5
// baseline (speedup 1.0000x reference)
#include <cuda_runtime.h>

// Online Normalization forward, fused dataflow kernel (v5).
// x: [B=32, H=64, W=64, C=256] channels-last, fp32.
//
// 128 CTAs x 1024 threads; CTA (t*4+q) owns quarter q of batch t (1 MB).
// No global barrier: batch t only needs partial sums of batches 0..t-1.
// Each batch publishes via a monotonic counter (graph-replay safe: exactly
// +4 per launch, launches serialize, epoch = old_value/4). Batch-0 CTAs
// normalize immediately; read & write streams overlap across CTAs.

#define AFWD 0.999f
#define EPS  1e-5f

constexpr int Bn   = 32;
constexpr int HW   = 64 * 64;       // 4096
constexpr int Cc   = 256;
constexpr int C4   = Cc / 4;        // 64
constexpr int NCTA = 128;           // 32 batches x 4 quarters
constexpr int ROWS = HW / 4;        // 1024 rows per CTA
constexpr int ITER = ROWS / 16;     // 64 rows per thread (16 row-groups)

__device__ float g_psum[Bn * 4 * Cc];
__device__ float g_psq [Bn * 4 * Cc];
__device__ unsigned int g_done[Bn];    // monotonic across graph replays

__global__ __launch_bounds__(1024, 1)
void onorm_fused(const float4* __restrict__ x4,
                 float4* __restrict__ o4,
                 const float* __restrict__ mu0,
                 const float* __restrict__ var0) {
    __shared__ float red_s[4096];
    __shared__ float red_q[4096];
    __shared__ float sm_mu[Cc];
    __shared__ float sm_rs[Cc];
    __shared__ unsigned int sm_epoch;

    const int tid = threadIdx.x;
    const int cta = blockIdx.x;
    const int c4  = tid & 63;          // float4 channel index
    const int rg  = tid >> 6;          // 0..15 row group
    const int t   = cta >> 2;          // batch owned by this CTA
    const int qq  = cta & 3;           // quarter of the batch

    const size_t base = ((size_t)t * HW + (size_t)qq * ROWS) * C4;
    const float4* p = x4 + base + (size_t)rg * C4 + c4;

    // ---------------- Pass 1: sync-free streaming accumulation ----------------
    float4 a = {0.f,0.f,0.f,0.f}, q = {0.f,0.f,0.f,0.f};
    #pragma unroll 8
    for (int i = 0; i < ITER; i++) {
        float4 v = p[(size_t)i * 16 * C4];
        a.x += v.x; a.y += v.y; a.z += v.z; a.w += v.w;
        q.x = fmaf(v.x, v.x, q.x); q.y = fmaf(v.y, v.y, q.y);
        q.z = fmaf(v.z, v.z, q.z); q.w = fmaf(v.w, v.w, q.w);
    }
    ((float4*)red_s)[rg * 64 + c4] = a;
    ((float4*)red_q)[rg * 64 + c4] = q;
    __syncthreads();
    if (tid < 64) {
        float4 sa = {0.f,0.f,0.f,0.f}, sq = {0.f,0.f,0.f,0.f};
        #pragma unroll
        for (int j = 0; j < 16; j++) {
            float4 va = ((float4*)red_s)[j * 64 + tid];
            float4 vq = ((float4*)red_q)[j * 64 + tid];
            sa.x += va.x; sa.y += va.y; sa.z += va.z; sa.w += va.w;
            sq.x += vq.x; sq.y += vq.y; sq.z += vq.z; sq.w += vq.w;
        }
        ((float4*)g_psum)[(t * 4 + qq) * 64 + tid] = sa;
        ((float4*)g_psq )[(t * 4 + qq) * 64 + tid] = sq;
    }
    __syncthreads();    // partial stores issued by tid<64 happen-before below

    // Publish: fence makes this CTA's partials globally visible, then bump
    // the batch counter. old/4 = replay epoch (exactly 4 adds per launch).
    if (tid == 0) {
        __threadfence();
        unsigned int old = atomicAdd(&g_done[t], 1u);
        sm_epoch = old >> 2;
    }
    __syncthreads();

    // ------------- Scan: pipelined wait on earlier batches ----------
    if (tid < Cc) {
        const int c = tid;
        const unsigned int need = (sm_epoch + 1u) * 4u;
        float mu  = mu0[c];
        float var = var0[c];
        const float inv = 1.0f / (float)HW;
        for (int tt = 0; tt < t; tt++) {
            if (c == 0) {
                while (*((volatile unsigned int*)&g_done[tt]) < need) { }
            }
            __syncwarp();
            // propagate readiness across the 8 scanning warps via warp 0's
            // poll + a light spin in other warps on the same flag
            if ((c & 31) == 0 && c != 0) {
                while (*((volatile unsigned int*)&g_done[tt]) < need) { }
            }
            __syncwarp();
            __threadfence();   // acquire: order flag read before data reads
            float s  = g_psum[(tt * 4 + 0) * Cc + c] + g_psum[(tt * 4 + 1) * Cc + c]
                     + g_psum[(tt * 4 + 2) * Cc + c] + g_psum[(tt * 4 + 3) * Cc + c];
            float s2 = g_psq [(tt * 4 + 0) * Cc + c] + g_psq [(tt * 4 + 1) * Cc + c]
                     + g_psq [(tt * 4 + 2) * Cc + c] + g_psq [(tt * 4 + 3) * Cc + c];
            const float mean = s * inv;
            const float vart = fmaf(-mean, mean, s2 * inv);
            const float d    = mean - mu;
            var = AFWD * var + (1.0f - AFWD) * vart
                + AFWD * (1.0f - AFWD) * d * d;
            mu  = fmaf(1.0f - AFWD, d, mu);
        }
        sm_mu[c] = mu;
        sm_rs[c] = rsqrtf(var + EPS);
    }
    __syncthreads();

    // ---------------- Pass 3: normalize own chunk (reverse order) -------------
    const float4 m = ((const float4*)sm_mu)[c4];
    const float4 r = ((const float4*)sm_rs)[c4];
    float4* o = o4 + base + (size_t)rg * C4 + c4;
    #pragma unroll 8
    for (int i = ITER - 1; i >= 0; i--) {
        float4 v = p[(size_t)i * 16 * C4];
        float4 w;
        w.x = (v.x - m.x) * r.x;
        w.y = (v.y - m.y) * r.y;
        w.z = (v.z - m.z) * r.z;
        w.w = (v.w - m.w) * r.w;
        __stcs(&o[(size_t)i * 16 * C4], w);
    }
}

extern "C" void kernel_launch(void* const* d_in, const int* in_sizes, int n_in,
                              void* d_out, int out_size) {
    const float* x    = (const float*)d_in[0];
    const float* mu0  = (const float*)d_in[1];
    const float* var0 = (const float*)d_in[2];
    float* out = (float*)d_out;

    onorm_fused<<<NCTA, 1024>>>((const float4*)x, (float4*)out, mu0, var0);
}

// round 6
// speedup vs baseline: 1.7600x; 1.7600x over previous
#include <cuda_runtime.h>

// Online Normalization forward, fused persistent kernel (v6 = v4 + smem-staged scan).
// x: [B=32, H=64, W=64, C=256] channels-last, fp32.
//
// 128 CTAs x 1024 threads. CTA (t*4+q) owns quarter q of batch t (1 MB).
// Pass 1: sync-free register accumulation + one smem reduce -> gmem partials.
// One grid barrier. Scan inputs are bulk-loaded into smem by all 1024
// threads (coalesced, quarters folded), then the 32-step EMA recurrence runs
// from smem. Pass 3: reverse-order re-read of own chunk (L2/L1 hits),
// streaming stores.

#define AFWD 0.999f
#define EPS  1e-5f

constexpr int Bn   = 32;
constexpr int HW   = 64 * 64;       // 4096
constexpr int Cc   = 256;
constexpr int C4   = Cc / 4;        // 64
constexpr int NCTA = 128;           // 32 batches x 4 quarters
constexpr int ROWS = HW / 4;        // 1024 rows per CTA
constexpr int ITER = ROWS / 16;     // 64 rows per thread (16 row-groups)

__device__ float g_psum[Bn * 4 * Cc];
__device__ float g_psq [Bn * 4 * Cc];
__device__ unsigned long long g_bar;   // monotonic across graph replays

// Dynamic smem (floats):
//   [0 : 16384)      union:  pass1 reduce  red_s[0:4096) red_q[4096:8192)
//                            scan staging  st_s[0:8192)  st_q[8192:16384)
//   [16384 : 16640)  sm_mu (own batch)
//   [16640 : 16896)  sm_rs (own batch)
constexpr int SMEM_FLOATS = 16896;     // 67.6 KB

__device__ __forceinline__ void grid_barrier() {
    __syncthreads();
    if (threadIdx.x == 0) {
        __threadfence();
        unsigned long long t = atomicAdd(&g_bar, 1ULL) + 1ULL;
        unsigned long long target = ((t + NCTA - 1ULL) / NCTA) * NCTA;
        while (*((volatile unsigned long long*)&g_bar) < target) { }
        __threadfence();
    }
    __syncthreads();
}

__global__ __launch_bounds__(1024, 1)
void onorm_fused(const float4* __restrict__ x4,
                 float4* __restrict__ o4,
                 const float* __restrict__ mu0,
                 const float* __restrict__ var0) {
    extern __shared__ float sm[];
    float* red_s = sm;                 // 4096 floats
    float* red_q = sm + 4096;          // 4096 floats
    float* st_s  = sm;                 // 8192 floats (after barrier)
    float* st_q  = sm + 8192;          // 8192 floats
    float* sm_mu = sm + 16384;         // 256 floats
    float* sm_rs = sm + 16640;         // 256 floats

    const int tid = threadIdx.x;
    const int cta = blockIdx.x;
    const int c4  = tid & 63;          // float4 channel index
    const int rg  = tid >> 6;          // 0..15 row group
    const int t   = cta >> 2;          // batch owned by this CTA
    const int qq  = cta & 3;           // quarter of the batch

    const size_t base = ((size_t)t * HW + (size_t)qq * ROWS) * C4;
    const float4* p = x4 + base + (size_t)rg * C4 + c4;

    // ---------------- Pass 1: sync-free streaming accumulation ----------------
    float4 a = {0.f,0.f,0.f,0.f}, q = {0.f,0.f,0.f,0.f};
    #pragma unroll 8
    for (int i = 0; i < ITER; i++) {
        float4 v = p[(size_t)i * 16 * C4];
        a.x += v.x; a.y += v.y; a.z += v.z; a.w += v.w;
        q.x = fmaf(v.x, v.x, q.x); q.y = fmaf(v.y, v.y, q.y);
        q.z = fmaf(v.z, v.z, q.z); q.w = fmaf(v.w, v.w, q.w);
    }
    ((float4*)red_s)[rg * 64 + c4] = a;
    ((float4*)red_q)[rg * 64 + c4] = q;
    __syncthreads();
    if (tid < 64) {
        float4 sa = {0.f,0.f,0.f,0.f}, sq = {0.f,0.f,0.f,0.f};
        #pragma unroll
        for (int j = 0; j < 16; j++) {
            float4 va = ((float4*)red_s)[j * 64 + tid];
            float4 vq = ((float4*)red_q)[j * 64 + tid];
            sa.x += va.x; sa.y += va.y; sa.z += va.z; sa.w += va.w;
            sq.x += vq.x; sq.y += vq.y; sq.z += vq.z; sq.w += vq.w;
        }
        ((float4*)g_psum)[(t * 4 + qq) * 64 + tid] = sa;
        ((float4*)g_psq )[(t * 4 + qq) * 64 + tid] = sq;
    }

    grid_barrier();   // orders partial stores before staging loads; also
                      // retires red_s/red_q before st_s/st_q reuse the space

    // ------- Stage: bulk parallel load of earlier batches' partials -----------
    // i encodes (tt, c): tt = i>>8, c = i&255. Fold the 4 quarter slots.
    for (int i = tid; i < t * Cc; i += 1024) {
        const int b = ((i >> 8) << 10) + (i & 255);   // (tt*4)*Cc + c
        st_s[i] = g_psum[b] + g_psum[b + 256] + g_psum[b + 512] + g_psum[b + 768];
        st_q[i] = g_psq [b] + g_psq [b + 256] + g_psq [b + 512] + g_psq [b + 768];
    }
    __syncthreads();

    // ------------- Scan: pure-arithmetic recurrence from smem -----------------
    if (tid < Cc) {
        const int c = tid;
        float mu  = mu0[c];
        float var = var0[c];
        const float inv = 1.0f / (float)HW;
        for (int tt = 0; tt < t; tt++) {
            const float mean = st_s[tt * Cc + c] * inv;
            const float vart = fmaf(-mean, mean, st_q[tt * Cc + c] * inv);
            const float d    = mean - mu;
            var = AFWD * var + (1.0f - AFWD) * vart
                + AFWD * (1.0f - AFWD) * d * d;
            mu  = fmaf(1.0f - AFWD, d, mu);
        }
        sm_mu[c] = mu;
        sm_rs[c] = rsqrtf(var + EPS);
    }
    __syncthreads();

    // ---------------- Pass 3: normalize own chunk (reverse order) -------------
    const float4 m = ((const float4*)sm_mu)[c4];
    const float4 r = ((const float4*)sm_rs)[c4];
    float4* o = o4 + base + (size_t)rg * C4 + c4;
    #pragma unroll 8
    for (int i = ITER - 1; i >= 0; i--) {
        float4 v = p[(size_t)i * 16 * C4];
        float4 w;
        w.x = (v.x - m.x) * r.x;
        w.y = (v.y - m.y) * r.y;
        w.z = (v.z - m.z) * r.z;
        w.w = (v.w - m.w) * r.w;
        __stcs(&o[(size_t)i * 16 * C4], w);
    }
}

extern "C" void kernel_launch(void* const* d_in, const int* in_sizes, int n_in,
                              void* d_out, int out_size) {
    const float* x    = (const float*)d_in[0];
    const float* mu0  = (const float*)d_in[1];
    const float* var0 = (const float*)d_in[2];
    float* out = (float*)d_out;

    static bool attr_set = false;
    if (!attr_set) {
        cudaFuncSetAttribute(onorm_fused,
                             cudaFuncAttributeMaxDynamicSharedMemorySize,
                             SMEM_FLOATS * sizeof(float));
        attr_set = true;
    }

    onorm_fused<<<NCTA, 1024, SMEM_FLOATS * sizeof(float)>>>(
        (const float4*)x, (float4*)out, mu0, var0);
}